// round 3
// baseline (speedup 1.0000x reference)
#include <cuda_runtime.h>
#include <cstdint>

// Problem constants (fixed by the dataset)
#define HOURS 168          // 24*7
#define B_SZ  32
#define N_SZ  128
#define E_SZ  64
// SU=100, SL=0, TU=1000, TL=0  ->  1/(SU-SL)=0.01, 1/(TU-TL)=0.001

// ---------------------------------------------------------------------------
// joint[b,n,e] = emb_t[(t-1 mod 168)+1, e] + emb_l[loc, e] + emb_u[user, e]
// One float4 per thread. 32*128*16 = 65536 float4 threads.
// ---------------------------------------------------------------------------
__global__ __launch_bounds__(256)
void joint_kernel(const int* __restrict__ traj,
                  const float4* __restrict__ emb_t,
                  const float4* __restrict__ emb_l,
                  const float4* __restrict__ emb_u,
                  float4* __restrict__ out_joint)
{
    int gid = blockIdx.x * blockDim.x + threadIdx.x;   // 0 .. 65535
    int row = gid >> 4;           // (b*N + n), 0..4095
    int e4  = gid & 15;           // float4 lane within the 64-float row

    int user = __ldg(&traj[row * 3 + 0]);
    int loc  = __ldg(&traj[row * 3 + 1]);
    int t    = __ldg(&traj[row * 3 + 2]);
    int t_idx = (t + HOURS - 1) % HOURS + 1;   // matches Python (t-1)%168 + 1

    float4 a = __ldg(&emb_t[t_idx * 16 + e4]);
    float4 b = __ldg(&emb_l[loc   * 16 + e4]);
    float4 c = __ldg(&emb_u[user  * 16 + e4]);

    float4 r;
    r.x = a.x + b.x + c.x;
    r.y = a.y + b.y + c.y;
    r.z = a.z + b.z + c.z;
    r.w = a.w + b.w + c.w;
    out_joint[gid] = r;
}

// ---------------------------------------------------------------------------
// delta[b,i,j,e] = base[m][e] + ds*cs[m][e] + dt*ct[m][e]
//   m  = (i < len_b) && (j < len_b)
//   base = emb_sl[m] + emb_tl[m]
//   cs   = (emb_su[m] - emb_sl[m]) / 100
//   ct   = (emb_tu[m] - emb_tl[m]) / 1000
// One block per (b,i) row: writes 128 j * 64 e floats = 32 KiB, float4 stores.
// ---------------------------------------------------------------------------
__global__ __launch_bounds__(256)
void delta_kernel(const float* __restrict__ mat,
                  const int*   __restrict__ traj_len,
                  const float4* __restrict__ emb_su,
                  const float4* __restrict__ emb_sl,
                  const float4* __restrict__ emb_tu,
                  const float4* __restrict__ emb_tl,
                  float4* __restrict__ out_delta)
{
    __shared__ float4 s_base[2][16];
    __shared__ float4 s_cs[2][16];
    __shared__ float4 s_ct[2][16];

    int tid = threadIdx.x;                  // 0..255
    int bi  = blockIdx.x;                   // b*N + i
    int b   = bi >> 7;

    if (tid < 32) {
        int m  = tid >> 4;                  // mask value 0/1
        int e4 = tid & 15;
        float4 sl = __ldg(&emb_sl[m * 16 + e4]);
        float4 su = __ldg(&emb_su[m * 16 + e4]);
        float4 tl = __ldg(&emb_tl[m * 16 + e4]);
        float4 tu = __ldg(&emb_tu[m * 16 + e4]);
        float4 bs, cs, ct;
        bs.x = sl.x + tl.x;  bs.y = sl.y + tl.y;  bs.z = sl.z + tl.z;  bs.w = sl.w + tl.w;
        cs.x = (su.x - sl.x) * 0.01f;  cs.y = (su.y - sl.y) * 0.01f;
        cs.z = (su.z - sl.z) * 0.01f;  cs.w = (su.w - sl.w) * 0.01f;
        ct.x = (tu.x - tl.x) * 0.001f; ct.y = (tu.y - tl.y) * 0.001f;
        ct.z = (tu.z - tl.z) * 0.001f; ct.w = (tu.w - tl.w) * 0.001f;
        s_base[m][e4] = bs;
        s_cs[m][e4]   = cs;
        s_ct[m][e4]   = ct;
    }
    __syncthreads();

    int len = __ldg(&traj_len[b]);
    int i   = bi & 127;
    bool vi = i < len;

    const float2* matrow = (const float2*)(mat) + (size_t)bi * N_SZ;  // [j] -> (ds, dt)
    float4* outrow = out_delta + (size_t)bi * (N_SZ * 16);            // 128 j * 16 float4

    #pragma unroll
    for (int iter = 0; iter < 8; iter++) {
        int idx = tid + iter * 256;     // 0..2047
        int j   = idx >> 4;
        int e4  = idx & 15;
        int m   = (vi && (j < len)) ? 1 : 0;

        float2 d  = __ldg(&matrow[j]);
        float  ds = d.x, dt = d.y;

        float4 bs = s_base[m][e4];
        float4 cs = s_cs[m][e4];
        float4 ct = s_ct[m][e4];

        float4 r;
        r.x = fmaf(dt, ct.x, fmaf(ds, cs.x, bs.x));
        r.y = fmaf(dt, ct.y, fmaf(ds, cs.y, bs.y));
        r.z = fmaf(dt, ct.z, fmaf(ds, cs.z, bs.z));
        r.w = fmaf(dt, ct.w, fmaf(ds, cs.w, bs.w));
        outrow[(size_t)j * 16 + e4] = r;
    }
}

// ---------------------------------------------------------------------------
// Launch: out = [joint (32*128*64 floats) | delta (32*128*128*64 floats)]
// ---------------------------------------------------------------------------
extern "C" void kernel_launch(void* const* d_in, const int* in_sizes, int n_in,
                              void* d_out, int out_size)
{
    const int*   traj     = (const int*)  d_in[0];
    const float* mat      = (const float*)d_in[1];
    const int*   traj_len = (const int*)  d_in[2];
    const float4* emb_t   = (const float4*)d_in[3];
    const float4* emb_l   = (const float4*)d_in[4];
    const float4* emb_u   = (const float4*)d_in[5];
    const float4* emb_su  = (const float4*)d_in[6];
    const float4* emb_sl  = (const float4*)d_in[7];
    const float4* emb_tu  = (const float4*)d_in[8];
    const float4* emb_tl  = (const float4*)d_in[9];

    float* out = (float*)d_out;
    float4* out_joint = (float4*)out;
    float4* out_delta = (float4*)(out + (size_t)B_SZ * N_SZ * E_SZ);

    // joint: 65536 float4 elements
    joint_kernel<<<256, 256>>>(traj, emb_t, emb_l, emb_u, out_joint);

    // delta: one block per (b, i)
    delta_kernel<<<B_SZ * N_SZ, 256>>>(mat, traj_len,
                                       emb_su, emb_sl, emb_tu, emb_tl,
                                       out_delta);
}

// round 4
// speedup vs baseline: 1.2627x; 1.2627x over previous
#include <cuda_runtime.h>
#include <cstdint>

// Problem constants (fixed by the dataset)
#define HOURS 168          // 24*7
#define B_SZ  32
#define N_SZ  128
#define E_SZ  64
// SU=100, SL=0, TU=1000, TL=0  ->  1/(SU-SL)=0.01, 1/(TU-TL)=0.001

#define DELTA_BLOCKS (B_SZ * N_SZ)          // 4096
#define JOINT_BLOCKS 256                    // 65536 float4 / 256 threads

// ---------------------------------------------------------------------------
// Fused kernel.
//  blocks [0, 4096):     delta rows — one block per (b,i), 128 j * 64 e floats
//  blocks [4096, 4352):  joint      — 256 float4 gather-sums per block
//
// delta[b,i,j,e] = base[m][e] + ds*cs[m][e] + dt*ct[m][e]
//   m    = (i < len_b) && (j < len_b)
//   base = emb_sl[m] + emb_tl[m]
//   cs   = (emb_su[m] - emb_sl[m]) / 100
//   ct   = (emb_tu[m] - emb_tl[m]) / 1000
// e4 = tid & 15 is CONSTANT per thread -> both mask variants of the
// coefficients live in registers; no smem in the hot loop.
// ---------------------------------------------------------------------------
__global__ __launch_bounds__(256)
void fused_kernel(const int*    __restrict__ traj,
                  const float*  __restrict__ mat,
                  const int*    __restrict__ traj_len,
                  const float4* __restrict__ emb_t,
                  const float4* __restrict__ emb_l,
                  const float4* __restrict__ emb_u,
                  const float4* __restrict__ emb_su,
                  const float4* __restrict__ emb_sl,
                  const float4* __restrict__ emb_tu,
                  const float4* __restrict__ emb_tl,
                  float4* __restrict__ out_joint,
                  float4* __restrict__ out_delta)
{
    int tid = threadIdx.x;
    int bid = blockIdx.x;

    if (bid < DELTA_BLOCKS) {
        // ----------------- delta path -----------------
        int bi = bid;                 // b*N + i
        int b  = bi >> 7;
        int i  = bi & 127;
        int len = __ldg(&traj_len[b]);
        bool vi = i < len;

        int e4 = tid & 15;            // constant float4 lane for this thread
        int j0 = tid >> 4;            // 0..15

        // Both mask variants of the coefficient tables, in registers.
        float4 sl0 = __ldg(&emb_sl[e4]);
        float4 sl1 = __ldg(&emb_sl[16 + e4]);
        float4 su0 = __ldg(&emb_su[e4]);
        float4 su1 = __ldg(&emb_su[16 + e4]);
        float4 tl0 = __ldg(&emb_tl[e4]);
        float4 tl1 = __ldg(&emb_tl[16 + e4]);
        float4 tu0 = __ldg(&emb_tu[e4]);
        float4 tu1 = __ldg(&emb_tu[16 + e4]);

        float4 bs0, cs0, ct0, bs1, cs1, ct1;
        bs0.x = sl0.x + tl0.x; bs0.y = sl0.y + tl0.y; bs0.z = sl0.z + tl0.z; bs0.w = sl0.w + tl0.w;
        bs1.x = sl1.x + tl1.x; bs1.y = sl1.y + tl1.y; bs1.z = sl1.z + tl1.z; bs1.w = sl1.w + tl1.w;
        cs0.x = (su0.x - sl0.x) * 0.01f;  cs0.y = (su0.y - sl0.y) * 0.01f;
        cs0.z = (su0.z - sl0.z) * 0.01f;  cs0.w = (su0.w - sl0.w) * 0.01f;
        cs1.x = (su1.x - sl1.x) * 0.01f;  cs1.y = (su1.y - sl1.y) * 0.01f;
        cs1.z = (su1.z - sl1.z) * 0.01f;  cs1.w = (su1.w - sl1.w) * 0.01f;
        ct0.x = (tu0.x - tl0.x) * 0.001f; ct0.y = (tu0.y - tl0.y) * 0.001f;
        ct0.z = (tu0.z - tl0.z) * 0.001f; ct0.w = (tu0.w - tl0.w) * 0.001f;
        ct1.x = (tu1.x - tl1.x) * 0.001f; ct1.y = (tu1.y - tl1.y) * 0.001f;
        ct1.z = (tu1.z - tl1.z) * 0.001f; ct1.w = (tu1.w - tl1.w) * 0.001f;

        const float2* matrow = (const float2*)(mat) + (size_t)bi * N_SZ;  // [j] -> (ds, dt)
        float4* outrow = out_delta + (size_t)bi * (N_SZ * 16);

        #pragma unroll
        for (int it = 0; it < 8; it++) {
            int j = j0 + (it << 4);
            bool m = vi && (j < len);

            float2 d  = __ldg(&matrow[j]);
            float  ds = d.x, dt = d.y;

            float4 bs, cs, ct;
            bs.x = m ? bs1.x : bs0.x; bs.y = m ? bs1.y : bs0.y;
            bs.z = m ? bs1.z : bs0.z; bs.w = m ? bs1.w : bs0.w;
            cs.x = m ? cs1.x : cs0.x; cs.y = m ? cs1.y : cs0.y;
            cs.z = m ? cs1.z : cs0.z; cs.w = m ? cs1.w : cs0.w;
            ct.x = m ? ct1.x : ct0.x; ct.y = m ? ct1.y : ct0.y;
            ct.z = m ? ct1.z : ct0.z; ct.w = m ? ct1.w : ct0.w;

            float4 r;
            r.x = fmaf(dt, ct.x, fmaf(ds, cs.x, bs.x));
            r.y = fmaf(dt, ct.y, fmaf(ds, cs.y, bs.y));
            r.z = fmaf(dt, ct.z, fmaf(ds, cs.z, bs.z));
            r.w = fmaf(dt, ct.w, fmaf(ds, cs.w, bs.w));

            // Streaming store: output is write-once, never re-read.
            __stcs(&outrow[(size_t)j * 16 + e4], r);
        }
    } else {
        // ----------------- joint path -----------------
        int gid = (bid - DELTA_BLOCKS) * 256 + tid;   // 0 .. 65535
        int row = gid >> 4;           // (b*N + n), 0..4095
        int e4  = gid & 15;

        int user = __ldg(&traj[row * 3 + 0]);
        int loc  = __ldg(&traj[row * 3 + 1]);
        int t    = __ldg(&traj[row * 3 + 2]);
        int t_idx = (t + HOURS - 1) % HOURS + 1;   // matches (t-1) % 168 + 1

        float4 a = __ldg(&emb_t[t_idx * 16 + e4]);
        float4 bb = __ldg(&emb_l[loc   * 16 + e4]);
        float4 c = __ldg(&emb_u[user  * 16 + e4]);

        float4 r;
        r.x = a.x + bb.x + c.x;
        r.y = a.y + bb.y + c.y;
        r.z = a.z + bb.z + c.z;
        r.w = a.w + bb.w + c.w;
        out_joint[gid] = r;
    }
}

// ---------------------------------------------------------------------------
// Launch: out = [joint (32*128*64 floats) | delta (32*128*128*64 floats)]
// ---------------------------------------------------------------------------
extern "C" void kernel_launch(void* const* d_in, const int* in_sizes, int n_in,
                              void* d_out, int out_size)
{
    const int*    traj     = (const int*)   d_in[0];
    const float*  mat      = (const float*) d_in[1];
    const int*    traj_len = (const int*)   d_in[2];
    const float4* emb_t    = (const float4*)d_in[3];
    const float4* emb_l    = (const float4*)d_in[4];
    const float4* emb_u    = (const float4*)d_in[5];
    const float4* emb_su   = (const float4*)d_in[6];
    const float4* emb_sl   = (const float4*)d_in[7];
    const float4* emb_tu   = (const float4*)d_in[8];
    const float4* emb_tl   = (const float4*)d_in[9];

    float* out = (float*)d_out;
    float4* out_joint = (float4*)out;
    float4* out_delta = (float4*)(out + (size_t)B_SZ * N_SZ * E_SZ);

    fused_kernel<<<DELTA_BLOCKS + JOINT_BLOCKS, 256>>>(
        traj, mat, traj_len,
        emb_t, emb_l, emb_u,
        emb_su, emb_sl, emb_tu, emb_tl,
        out_joint, out_delta);
}